// round 9
// baseline (speedup 1.0000x reference)
#include <cuda_runtime.h>
#include <math.h>

// Problem constants
#define E      1024      // n_embd
#define DH     64        // d_head
#define NF     80        // fused GEMM cols: 8 (pq) + 8 (pk) + 64 (v)
#define MT     128       // M-tile rows per CTA
#define KC     32        // K chunk
#define NROWS  32768     // b*t = 4*8192
#define NTILES 256       // NROWS / MT
#define NBATCH 4
#define TPB    8192      // tokens per batch

typedef unsigned long long u64;

// ---------------- scratch (static __device__, no allocation) ----------------
__device__ float g_Wall[E * NF];          // fused weights [k][80]
__device__ float g_call[NF];              // fused bias row [80]
__device__ float g_qP[NROWS * 16];        // query features (2 MB)
__device__ float g_Spart[NTILES * 1024];  // per-CTA partial S (deterministic)
__device__ float g_S[NBATCH * 1024];      // reduced S [b][16][64]

__device__ __forceinline__ void ffma2(u64& d, u64 a, u64 b) {
    asm("fma.rn.f32x2 %0, %1, %2, %0;" : "+l"(d) : "l"(a), "l"(b));
}

// ---------------- kernel 1: fold weights --------------------------------
// Wall[:, 0:8]  = Wq @ w        (p_q = x @ (Wq w) + bq·w)
// Wall[:, 8:16] = Wk @ w
// Wall[:,16:80] = Wv
__global__ void prep_kernel(const float* __restrict__ w,
                            const float* __restrict__ Wq, const float* __restrict__ bq,
                            const float* __restrict__ Wk, const float* __restrict__ bk,
                            const float* __restrict__ Wv, const float* __restrict__ bv) {
    int k = blockIdx.x;
    int n = threadIdx.x;
    if (n >= NF) return;
    float outv;
    if (n < 8) {
        float s = 0.f;
        #pragma unroll 8
        for (int d = 0; d < DH; d++) s += Wq[k * DH + d] * w[d * 8 + n];
        outv = s;
    } else if (n < 16) {
        float s = 0.f;
        #pragma unroll 8
        for (int d = 0; d < DH; d++) s += Wk[k * DH + d] * w[d * 8 + (n - 8)];
        outv = s;
    } else {
        outv = Wv[k * DH + (n - 16)];
    }
    g_Wall[k * NF + n] = outv;
    if (k == 0) {
        float c;
        if (n < 8)       { float s = 0.f; for (int d = 0; d < DH; d++) s += bq[d] * w[d * 8 + n];       c = s; }
        else if (n < 16) { float s = 0.f; for (int d = 0; d < DH; d++) s += bk[d] * w[d * 8 + (n - 8)]; c = s; }
        else c = bv[n - 16];
        g_call[n] = c;
    }
}

// ---------------- kernel 2: fused GEMM + feature epilogue + partial S ----
// CTA: 128 threads, tile M=128 x N=80, K looped in KC=32 chunks.
// Thread micro-tile 8 rows x 10 cols, accumulated as 5 f32x2 pairs per row.
// x tile stored DUPLICATED ({a,a}) in smem so FFMA2 needs no pack ops.
// Software pipeline: next k-tile's LDGs are issued to registers BEFORE the
// compute phase, hiding DRAM latency under the FFMA2 block. FP order
// identical to the unpipelined version.
// launch_bounds(128, 2): 2 CTAs/SM so STS/sync bubbles are covered too.
__global__ __launch_bounds__(128, 2) void favor_main(const float* __restrict__ x) {
    __shared__ __align__(16) unsigned char smem[44032];
    // GEMM phase layout
    float2 (*sA)[KC + 1] = reinterpret_cast<float2(*)[KC + 1]>(smem);                 // [128][33] dup pairs (33792 B)
    float2 (*sB)[40]     = reinterpret_cast<float2(*)[40]>(smem + 128 * (KC + 1) * 8); // [32][40]  (10240 B)
    // epilogue overlay
    float  (*sP)[84]     = reinterpret_cast<float(*)[84]>(smem);                       // [128][84] (43008 B)

    const int tid  = threadIdx.x;
    const int row0 = blockIdx.x * MT;
    const int rg   = tid >> 3;   // 0..15 (row group of 8)
    const int cg   = tid & 7;    // 0..7  (col group of 10 = 5 pairs)

    u64 acc[8][5];
    #pragma unroll
    for (int i = 0; i < 8; i++)
        #pragma unroll
        for (int j = 0; j < 5; j++) acc[i][j] = 0ull;

    const float* xb = x + (size_t)row0 * E;

    // ---- prefetch tile kt=0 into registers
    float4 pa[8], pb[5];
    #pragma unroll
    for (int i = 0; i < 8; i++) {
        int idx = i * 128 + tid;
        int r   = idx >> 3;
        int c4  = idx & 7;
        pa[i] = *reinterpret_cast<const float4*>(xb + (size_t)r * E + c4 * 4);
    }
    #pragma unroll
    for (int i = 0; i < 5; i++) {
        int idx = i * 128 + tid;
        int kk  = idx / 20;
        int c4  = idx % 20;
        pb[i] = *reinterpret_cast<const float4*>(&g_Wall[kk * NF + c4 * 4]);
    }

    for (int kt = 0; kt < E; kt += KC) {
        // ---- store prefetched x tile (duplicated into float2 pairs)
        #pragma unroll
        for (int i = 0; i < 8; i++) {
            int idx = i * 128 + tid;
            int r   = idx >> 3;
            int c4  = idx & 7;
            float4 v = pa[i];
            float2* dst = &sA[r][c4 * 4];
            dst[0] = make_float2(v.x, v.x);
            dst[1] = make_float2(v.y, v.y);
            dst[2] = make_float2(v.z, v.z);
            dst[3] = make_float2(v.w, v.w);
        }
        // ---- store prefetched W tile
        #pragma unroll
        for (int i = 0; i < 5; i++) {
            int idx = i * 128 + tid;
            int kk  = idx / 20;
            int c4  = idx % 20;
            float4 v = pb[i];
            sB[kk][c4 * 2]     = make_float2(v.x, v.y);
            sB[kk][c4 * 2 + 1] = make_float2(v.z, v.w);
        }
        __syncthreads();

        // ---- issue next tile's global loads (overlap with compute below)
        if (kt + KC < E) {
            #pragma unroll
            for (int i = 0; i < 8; i++) {
                int idx = i * 128 + tid;
                int r   = idx >> 3;
                int c4  = idx & 7;
                pa[i] = *reinterpret_cast<const float4*>(xb + (size_t)r * E + (kt + KC) + c4 * 4);
            }
            #pragma unroll
            for (int i = 0; i < 5; i++) {
                int idx = i * 128 + tid;
                int kk  = idx / 20;
                int c4  = idx % 20;
                pb[i] = *reinterpret_cast<const float4*>(&g_Wall[(kt + KC + kk) * NF + c4 * 4]);
            }
        }

        // ---- compute over current smem tiles
        #pragma unroll 4
        for (int k = 0; k < KC; k++) {
            u64 aa[8], bb[5];
            #pragma unroll
            for (int i = 0; i < 8; i++)
                aa[i] = *reinterpret_cast<const u64*>(&sA[rg * 8 + i][k]);
            #pragma unroll
            for (int j = 0; j < 5; j++)
                bb[j] = *reinterpret_cast<const u64*>(&sB[k][cg * 5 + j]);
            #pragma unroll
            for (int i = 0; i < 8; i++)
                #pragma unroll
                for (int j = 0; j < 5; j++)
                    ffma2(acc[i][j], aa[i], bb[j]);
        }
        __syncthreads();
    }

    // ---- stage P = acc + bias into smem
    #pragma unroll
    for (int i = 0; i < 8; i++) {
        int r = rg * 8 + i;
        #pragma unroll
        for (int j = 0; j < 5; j++) {
            int col = cg * 10 + 2 * j;
            float2 pv = *reinterpret_cast<float2*>(&acc[i][j]);
            sP[r][col]     = pv.x + g_call[col];
            sP[r][col + 1] = pv.y + g_call[col + 1];
        }
    }
    __syncthreads();

    // ---- feature maps: one row per thread (row-private, in-place rewrite)
    {
        const float INV = 0.3535533905932738f;  // 1/sqrt(8)
        int r = tid;
        float qs[8], qc[8], ks[8], kc[8];
        #pragma unroll
        for (int f = 0; f < 8; f++) sincosf(sP[r][f],     &qs[f], &qc[f]);
        #pragma unroll
        for (int f = 0; f < 8; f++) sincosf(sP[r][8 + f], &ks[f], &kc[f]);
        float4* gq = reinterpret_cast<float4*>(&g_qP[(size_t)(row0 + r) * 16]);
        gq[0] = make_float4(qc[0] * INV, qc[1] * INV, qc[2] * INV, qc[3] * INV);
        gq[1] = make_float4(qc[4] * INV, qc[5] * INV, qc[6] * INV, qc[7] * INV);
        gq[2] = make_float4(qs[0] * INV, qs[1] * INV, qs[2] * INV, qs[3] * INV);
        gq[3] = make_float4(qs[4] * INV, qs[5] * INV, qs[6] * INV, qs[7] * INV);
        // Kp features replace pq/pk in place (cols 0..15); v stays at 16..79
        #pragma unroll
        for (int f = 0; f < 8; f++) { sP[r][f] = kc[f] * INV; sP[r][8 + f] = ks[f] * INV; }
    }
    __syncthreads();

    // ---- per-CTA partial S[16][64] = sum_r Kp[r][f] * v[r][d]
    {
        int f  = tid >> 3;
        int d0 = (tid & 7) * 8;
        float s[8];
        #pragma unroll
        for (int j = 0; j < 8; j++) s[j] = 0.f;
        for (int r = 0; r < MT; r++) {
            float  kp = sP[r][f];
            float4 v0 = *reinterpret_cast<const float4*>(&sP[r][16 + d0]);
            float4 v1 = *reinterpret_cast<const float4*>(&sP[r][16 + d0 + 4]);
            s[0] += kp * v0.x; s[1] += kp * v0.y; s[2] += kp * v0.z; s[3] += kp * v0.w;
            s[4] += kp * v1.x; s[5] += kp * v1.y; s[6] += kp * v1.z; s[7] += kp * v1.w;
        }
        float* dst = &g_Spart[(size_t)blockIdx.x * 1024 + f * 64 + d0];
        #pragma unroll
        for (int j = 0; j < 8; j++) dst[j] = s[j];
    }
}

// ---------------- kernel 3: reduce partial S (deterministic) -------------
__global__ void reduce_S_kernel() {
    int idx = blockIdx.x * 256 + threadIdx.x;   // 0..4095
    int bi  = idx >> 10;
    int e   = idx & 1023;
    float s = 0.f;
    const float* src = &g_Spart[(size_t)bi * 64 * 1024 + e];
    #pragma unroll 8
    for (int j = 0; j < 64; j++) s += src[j * 1024];
    g_S[idx] = s;
}

// ---------------- kernel 4: y = qP @ S -----------------------------------
__global__ __launch_bounds__(256) void final_kernel(float* __restrict__ out) {
    __shared__ float4 sS[256];                  // 16 features x 16 float4 (64 cols)
    int tid = threadIdx.x;
    int row = blockIdx.x * 256 + tid;           // block stays within one batch (256 | 8192)
    int bi  = row >> 13;
    sS[tid] = reinterpret_cast<const float4*>(&g_S[bi * 1024])[tid];
    __syncthreads();

    float qf[16];
    const float4* qp4 = reinterpret_cast<const float4*>(&g_qP[(size_t)row * 16]);
    #pragma unroll
    for (int i = 0; i < 4; i++) {
        float4 q = qp4[i];
        qf[i * 4] = q.x; qf[i * 4 + 1] = q.y; qf[i * 4 + 2] = q.z; qf[i * 4 + 3] = q.w;
    }
    float4 o[16];
    #pragma unroll
    for (int d = 0; d < 16; d++) o[d] = make_float4(0.f, 0.f, 0.f, 0.f);
    #pragma unroll
    for (int f = 0; f < 16; f++) {
        float q = qf[f];
        #pragma unroll
        for (int d = 0; d < 16; d++) {
            float4 sv = sS[f * 16 + d];
            o[d].x += q * sv.x; o[d].y += q * sv.y; o[d].z += q * sv.z; o[d].w += q * sv.w;
        }
    }
    float4* po = reinterpret_cast<float4*>(out + (size_t)row * 64);
    #pragma unroll
    for (int d = 0; d < 16; d++) po[d] = o[d];
}

// ---------------- launch ---------------------------------------------------
extern "C" void kernel_launch(void* const* d_in, const int* in_sizes, int n_in,
                              void* d_out, int out_size) {
    const float* x  = (const float*)d_in[0];
    const float* w  = (const float*)d_in[1];
    const float* Wq = (const float*)d_in[2];
    const float* bq = (const float*)d_in[3];
    const float* Wk = (const float*)d_in[4];
    const float* bk = (const float*)d_in[5];
    const float* Wv = (const float*)d_in[6];
    const float* bv = (const float*)d_in[7];
    float* out = (float*)d_out;

    prep_kernel<<<E, 128>>>(w, Wq, bq, Wk, bk, Wv, bv);
    favor_main<<<NTILES, 128>>>(x);
    reduce_S_kernel<<<16, 256>>>();
    final_kernel<<<128, 256>>>(out);
}